// round 6
// baseline (speedup 1.0000x reference)
#include <cuda_runtime.h>
#include <cuda_fp16.h>

#define BH   16
#define LQ   512
#define LK   512
#define DD   64
#define D16  48          // d-slice on MUFU f16x2 tanh path
#define D32  16          // d-slice on FMA-pipe Pade path
#define TQ   16
#define TK   64
#define W16  25          // wk16 row stride in u32 (24 data + 1 pad, odd -> conflict-free)
#define W32  18          // wk32/wq32 row stride in floats (16 data + 2 pad, 8B-aligned rows)

// Projected tensors (device globals: no allocation).
__device__ __half2 g_Wq16[BH * LQ * D16 / 2];
__device__ __half2 g_Wk16[BH * LK * D16 / 2];
__device__ float   g_Wq32[BH * LQ * D32];
__device__ float   g_Wk32[BH * LK * D32];

// ---------------------------------------------------------------------------
// Packed helpers
// ---------------------------------------------------------------------------
__device__ __forceinline__ __half2 tanh2(__half2 x) {
    unsigned xi = *(unsigned*)&x, yi;
    asm("tanh.approx.f16x2 %0, %1;" : "=r"(yi) : "r"(xi));
    return *(__half2*)&yi;
}

__device__ __forceinline__ void acc_flush(double& acc, __half2 h) {
    unsigned hi = *(unsigned*)&h;
    asm("{\n\t"
        ".reg .f16 l, m;\n\t"
        ".reg .f32 fl, fh;\n\t"
        ".reg .b64 p;\n\t"
        "mov.b32 {l, m}, %1;\n\t"
        "cvt.f32.f16 fl, l;\n\t"
        "cvt.f32.f16 fh, m;\n\t"
        "mov.b64 p, {fl, fh};\n\t"
        "add.rn.f32x2 %0, %0, p;\n\t"
        "}" : "+d"(acc) : "r"(hi));
}

__device__ __forceinline__ double f2x2(float lo, float hi) {
    double r; asm("mov.b64 %0, {%1, %2};" : "=d"(r) : "f"(lo), "f"(hi)); return r;
}
__device__ __forceinline__ double addx2(double a, double b) {
    double r; asm("add.rn.f32x2 %0, %1, %2;" : "=d"(r) : "d"(a), "d"(b)); return r;
}
__device__ __forceinline__ double mulx2(double a, double b) {
    double r; asm("mul.rn.f32x2 %0, %1, %2;" : "=d"(r) : "d"(a), "d"(b)); return r;
}
__device__ __forceinline__ double fmx2(double a, double b, double c) {
    double r; asm("fma.rn.f32x2 %0, %1, %2, %3;" : "=d"(r) : "d"(a), "d"(b), "d"(c)); return r;
}
// Reciprocal seed of +D from bits of (-D): 0xFEF311C3 - bits(-D) == 0x7EF311C3 - bits(D).
__device__ __forceinline__ double rcp_seed_from_neg(double dn) {
    unsigned lo, hi;
    asm("mov.b64 {%0, %1}, %2;" : "=r"(lo), "=r"(hi) : "d"(dn));
    lo = 0xFEF311C3u - lo;
    hi = 0xFEF311C3u - hi;
    double r; asm("mov.b64 %0, {%1, %2};" : "=d"(r) : "r"(lo), "r"(hi)); return r;
}

// ---------------------------------------------------------------------------
// Fused projection kernel (fp32 compute; split fp16/fp32 outputs).
//   blocks [0,256):    Wq = Q*W1 + b1     blocks [256,512): Wk = K*W2 + b2
//   e in [0,48)  -> half2 arrays (MUFU path);  e in [48,64) -> f32 arrays.
// ---------------------------------------------------------------------------
__global__ __launch_bounds__(256) void proj_fused_kernel(
    const float* __restrict__ Q, const float* __restrict__ K,
    const float* __restrict__ W1, const float* __restrict__ b1,
    const float* __restrict__ W2, const float* __restrict__ b2)
{
    __shared__ float Ws[DD][DD];
    __shared__ float Xs[32][DD + 1];

    const int  tid  = threadIdx.x;
    const bool isK  = (blockIdx.x >= 256);
    const int  blk  = isK ? (blockIdx.x - 256) : blockIdx.x;
    const int  rowBase = blk * 32;

    const float* __restrict__ X  = isK ? K  : Q;
    const float* __restrict__ W  = isK ? W2 : W1;
    const float* __restrict__ bb = isK ? b2 : b1;
    __half2* __restrict__ Out16  = isK ? g_Wk16 : g_Wq16;
    float*   __restrict__ Out32  = isK ? g_Wk32 : g_Wq32;

    {
        const float4* src = (const float4*)W;
        float4* dst = (float4*)&Ws[0][0];
#pragma unroll
        for (int t = 0; t < 4; t++) dst[tid + t * 256] = src[tid + t * 256];
    }
#pragma unroll
    for (int t = 0; t < 8; t++) {
        int i = tid + t * 256;
        int r = i >> 6, c = i & 63;
        Xs[r][c] = X[(size_t)(rowBase + r) * DD + c];
    }
    __syncthreads();

    const int lane = tid & 31;
    const int eg   = tid >> 5;

    float acc[8];
#pragma unroll
    for (int j = 0; j < 8; j++) acc[j] = __ldg(&bb[eg * 8 + j]);

#pragma unroll
    for (int d = 0; d < DD; d++) {
        const float xv = Xs[lane][d];
        const float4 w0 = *(const float4*)&Ws[d][eg * 8];
        const float4 w1 = *(const float4*)&Ws[d][eg * 8 + 4];
        acc[0] += xv * w0.x; acc[1] += xv * w0.y;
        acc[2] += xv * w0.z; acc[3] += xv * w0.w;
        acc[4] += xv * w1.x; acc[5] += xv * w1.y;
        acc[6] += xv * w1.z; acc[7] += xv * w1.w;
    }

    __syncthreads();
#pragma unroll
    for (int j = 0; j < 8; j++) Xs[lane][eg * 8 + j] = acc[j];
    __syncthreads();

    // f16 part: 32 rows x 24 half2 = 768, coalesced-ish
#pragma unroll
    for (int t = 0; t < 3; t++) {
        int i = tid + t * 256;
        int r = i / (D16 / 2), c = i % (D16 / 2);
        Out16[(size_t)(rowBase + r) * (D16 / 2) + c] =
            __floats2half2_rn(Xs[r][2 * c], Xs[r][2 * c + 1]);
    }
    // f32 part: 32 rows x 16 f32 = 512
#pragma unroll
    for (int t = 0; t < 2; t++) {
        int i = tid + t * 256;
        int r = i >> 4, c = i & 15;
        Out32[(size_t)(rowBase + r) * D32 + c] = Xs[r][D16 + c];
    }
}

// ---------------------------------------------------------------------------
// Main kernel: tile 16q x 64k, micro-tile 2x2; 4096 blocks.
//   d in [0,48):  f16x2 MUFU tanh path (pipe: MUFU)
//   d in [48,64): Pade [5/4] tanh, packed f32x2, magic-seed Newton reciprocal
//                 (pipes: FMA + ALU — zero MUFU)
// ---------------------------------------------------------------------------
__global__ __launch_bounds__(256, 4) void attn_main_kernel(
    const float* __restrict__ Vv, const float* __restrict__ bV,
    float* __restrict__ out)
{
    __shared__ unsigned wq16_s[TQ * (D16 / 2)];          // 16 x 24 u32
    __shared__ unsigned wk16_s[TK * W16];                // 64 x 25 u32 (pad)
    __shared__ __align__(8) float wq32_s[TQ * W32];      // 16 x 18 f32 (pad)
    __shared__ __align__(8) float wk32_s[TK * W32];      // 64 x 18 f32 (pad)
    __shared__ __half2 v16_s[D16 / 2];
    __shared__ __align__(8) float v32_s[D32];

    const int bh    = blockIdx.z;
    const int qBase = blockIdx.y * TQ;
    const int kBase = blockIdx.x * TK;
    const int tid   = threadIdx.x;

    // ---- fill smem ----
    {
        const unsigned* src = (const unsigned*)(g_Wq16 + (size_t)(bh * LQ + qBase) * (D16 / 2));
        for (int i = tid; i < TQ * (D16 / 2); i += 256) wq16_s[i] = src[i];
    }
    {
        const unsigned* src = (const unsigned*)(g_Wk16 + (size_t)(bh * LK + kBase) * (D16 / 2));
#pragma unroll
        for (int t = 0; t < 6; t++) {                    // 6*256 = 1536 = 64*24
            int i = tid + t * 256;
            int r = i / (D16 / 2), c = i % (D16 / 2);
            wk16_s[r * W16 + c] = src[r * (D16 / 2) + c];
        }
    }
    {
        const float* src = g_Wq32 + (size_t)(bh * LQ + qBase) * D32;
        for (int i = tid; i < TQ * D32; i += 256) {
            int r = i >> 4, c = i & 15;
            wq32_s[r * W32 + c] = src[i];
        }
    }
    {
        const float* src = g_Wk32 + (size_t)(bh * LK + kBase) * D32;
#pragma unroll
        for (int t = 0; t < 4; t++) {                    // 4*256 = 1024 = 64*16
            int i = tid + t * 256;
            int r = i >> 4, c = i & 15;
            wk32_s[r * W32 + c] = src[i];
        }
    }
    if (tid < D16 / 2) v16_s[tid] = __floats2half2_rn(Vv[2 * tid], Vv[2 * tid + 1]);
    else if (tid >= 32 && tid < 32 + D32) v32_s[tid - 32] = Vv[D16 + (tid - 32)];
    __syncthreads();

    const int ty = tid >> 5;            // warp id -> q rows ty*2, ty*2+1
    const int tx = tid & 31;            // k lane; k = j*32 + tx

    double acc[2][2];
#pragma unroll
    for (int i = 0; i < 2; i++)
#pragma unroll
        for (int j = 0; j < 2; j++) acc[i][j] = 0.0;

    // ================= f16x2 MUFU path: d in [0,48), groups of 4 =================
#pragma unroll 4
    for (int c2 = 0; c2 < D16 / 2; c2 += 2) {
        const __half2 v01 = v16_s[c2];
        const __half2 v23 = v16_s[c2 + 1];

        __half2 wq01[2], wq23[2];
#pragma unroll
        for (int i = 0; i < 2; i++) {
            unsigned a = wq16_s[(ty * 2 + i) * (D16 / 2) + c2];       // broadcast
            unsigned b = wq16_s[(ty * 2 + i) * (D16 / 2) + c2 + 1];
            wq01[i] = *(__half2*)&a; wq23[i] = *(__half2*)&b;
        }
        __half2 wk01[2], wk23[2];
#pragma unroll
        for (int j = 0; j < 2; j++) {
            unsigned a = wk16_s[(j * 32 + tx) * W16 + c2];            // conflict-free
            unsigned b = wk16_s[(j * 32 + tx) * W16 + c2 + 1];
            wk01[j] = *(__half2*)&a; wk23[j] = *(__half2*)&b;
        }

#pragma unroll
        for (int i = 0; i < 2; i++)
#pragma unroll
            for (int j = 0; j < 2; j++) {
                __half2 t01 = tanh2(__hadd2(wq01[i], wk01[j]));
                __half2 t23 = tanh2(__hadd2(wq23[i], wk23[j]));
                __half2 h   = __hfma2(t23, v23, __hmul2(t01, v01));
                acc_flush(acc[i][j], h);
            }
    }

    // ================= Pade path: d in [48,64), packed f32 pairs =================
    const double C105  = f2x2(105.0f, 105.0f);
    const double C945  = f2x2(945.0f, 945.0f);
    const double CM15  = f2x2(-15.0f, -15.0f);
    const double CM420 = f2x2(-420.0f, -420.0f);
    const double CM945 = f2x2(-945.0f, -945.0f);
    const double ONE   = f2x2(1.0f, 1.0f);

#pragma unroll 2
    for (int dp = 0; dp < D32 / 2; dp++) {
        const double vp = *(const double*)&v32_s[2 * dp];

        double wqp[2], wkp[2];
#pragma unroll
        for (int i = 0; i < 2; i++)
            wqp[i] = *(const double*)&wq32_s[(ty * 2 + i) * W32 + 2 * dp];  // broadcast
#pragma unroll
        for (int j = 0; j < 2; j++)
            wkp[j] = *(const double*)&wk32_s[(j * 32 + tx) * W32 + 2 * dp]; // 2-phase

#pragma unroll
        for (int i = 0; i < 2; i++)
#pragma unroll
            for (int j = 0; j < 2; j++) {
                double x  = addx2(wqp[i], wkp[j]);
                double z  = mulx2(x, x);
                double n  = fmx2(addx2(z, C105), z, C945);     // N = 945+105z+z^2
                double dn = fmx2(fmx2(z, CM15, CM420), z, CM945); // -D
                double xn = mulx2(x, n);
                double r  = rcp_seed_from_neg(dn);             // ~1/D (±5%)
                r = fmx2(r, fmx2(dn, r, ONE), r);              // Newton 1
                r = fmx2(r, fmx2(dn, r, ONE), r);              // Newton 2
                acc[i][j] = fmx2(mulx2(xn, r), vp, acc[i][j]); // += tanh * v
            }
    }

    // ---- epilogue ----
    const float bv = bV[0];
#pragma unroll
    for (int i = 0; i < 2; i++) {
        const size_t rowOff = (size_t)(bh * LQ + qBase + ty * 2 + i) * LK + kBase;
#pragma unroll
        for (int j = 0; j < 2; j++) {
            float2 a = *(float2*)&acc[i][j];
            out[rowOff + j * 32 + tx] = a.x + a.y + bv;        // coalesced
        }
    }
}

// ---------------------------------------------------------------------------
// Launch
// ---------------------------------------------------------------------------
extern "C" void kernel_launch(void* const* d_in, const int* in_sizes, int n_in,
                              void* d_out, int out_size)
{
    const float* Q  = (const float*)d_in[0];
    const float* K  = (const float*)d_in[1];
    const float* W1 = (const float*)d_in[2];
    const float* b1 = (const float*)d_in[3];
    const float* W2 = (const float*)d_in[4];
    const float* b2 = (const float*)d_in[5];
    const float* V  = (const float*)d_in[6];
    const float* bV = (const float*)d_in[7];
    float* out = (float*)d_out;

    proj_fused_kernel<<<512, 256>>>(Q, K, W1, b1, W2, b2);

    dim3 grid(LK / TK, LQ / TQ, BH);                     // 8 x 32 x 16 = 4096
    attn_main_kernel<<<grid, 256>>>(V, bV, out);
}